// round 9
// baseline (speedup 1.0000x reference)
#include <cuda_runtime.h>
#include <math.h>

// Shapes (fixed by dataset):
//   features: [B=2, C=512, H=50, W=64] float32
//   roiss   : [B=2, N=128, 4]          float32
//   out     : [B, N, C]                float32
#define BB 2
#define CC 512
#define HH 50
#define WW 64
#define NN 128
#define HWSZ (HH * WW)   // 3200

// ---------------------------------------------------------------------------
// Fused ROI max-pool, single-wave version.
//   grid  = (B*N, 2) = 512 blocks — blockIdx.y = 256-channel tile
//   block = 512 (16 warps); warp: 8 channels x 4 float2 chunks;
//   each thread ALSO handles channel c+128 -> 2 channels, 16 LDG.64 in
//   flight (MLP=16). 4 blocks/SM x 148 SMs = 592 slots >= 512 -> ONE wave.
// Window width <= 7 -> 8-float span aligned to 2 covers it (4 float2 chunks).
// y1 folded into base pointer -> row loads use compile-time immediates.
// ---------------------------------------------------------------------------
struct Box { int x1, xe, y1, ye, xa; };

__global__ __launch_bounds__(512, 4) void roipool_fused_kernel(
    const float* __restrict__ feat,
    const float* __restrict__ rois,
    float* __restrict__ out)
{
    const int bn    = blockIdx.x;           // 0 .. B*N-1
    const int b     = bn / NN;
    const int w     = threadIdx.x >> 5;     // warp 0..15
    const int lane  = threadIdx.x & 31;
    const int csub  = lane >> 2;            // 0..7  channel within warp
    const int chunk = lane & 3;             // 0..3  float2 chunk
    const int c     = blockIdx.y * 256 + w * 8 + csub;   // second is c+128

    __shared__ Box sbox;

    if (threadIdx.x == 0) {
        // --- box computation (byte-identical to jax reference path) ---
        const float4 r = reinterpret_cast<const float4*>(rois)[bn];
        const float nx1 = __fmul_rn(__fdiv_rn(r.x, 1024.0f), (float)WW);
        const float ny1 = __fmul_rn(__fdiv_rn(r.y,  800.0f), (float)HH);
        const float nx2 = __fmul_rn(__fdiv_rn(r.z, 1024.0f), (float)WW);
        const float ny2 = __fmul_rn(__fdiv_rn(r.w,  800.0f), (float)HH);

        int x1 = max((int)floorf(nx1), 0);
        int y1 = max((int)floorf(ny1), 0);
        int x2 = max((int)ceilf(nx2), 0);
        int y2 = max((int)ceilf(ny2), 0);

        if (x1 == 0 && x2 == 0) x2 = 1;
        if (y1 == 0 && y2 == 0) y2 = 1;
        if (x1 >= WW) x1 = WW - 1;
        if (y1 >= HH) y1 = HH - 1;

        sbox.x1 = x1;
        sbox.xe = min(x2, WW);
        sbox.y1 = y1;
        sbox.ye = min(y2, HH);
        sbox.xa = x1 & ~1;                  // 8B-aligned window start
    }
    __syncthreads();

    const int x1 = sbox.x1, xe = sbox.xe, y1 = sbox.y1, ye = sbox.ye;
    const int hgt = ye - y1;                // rows in window (<= 7 here)
    const int xb  = sbox.xa + chunk * 2;    // this thread's chunk start
    const bool chunk_ok = (xb < xe);

    // Fold y1 into base pointers: row j is a compile-time byte offset j*W*4.
    const float* baseA = feat + ((size_t)(b * CC + c)) * HWSZ
                              + y1 * WW + xb;
    const float* baseB = baseA + (size_t)128 * HWSZ;    // channel c+128

    float a0 = -INFINITY, a1 = -INFINITY;   // channel c
    float b0 = -INFINITY, b1 = -INFINITY;   // channel c+128

    // 16 independent predicated LDG.64 (2 channels x 8 rows), MLP=16.
    #pragma unroll
    for (int j = 0; j < 8; ++j) {
        if (chunk_ok && j < hgt) {
            const float2 vA = *reinterpret_cast<const float2*>(baseA + j * WW);
            const float2 vB = *reinterpret_cast<const float2*>(baseB + j * WW);
            a0 = fmaxf(a0, vA.x);
            a1 = fmaxf(a1, vA.y);
            b0 = fmaxf(b0, vB.x);
            b1 = fmaxf(b1, vB.y);
        }
    }
    // Safety tails (never taken with these shapes: height<=7, width<=7)
    for (int j = 8; j < hgt; ++j) {
        if (chunk_ok) {
            const float2 vA = *reinterpret_cast<const float2*>(baseA + j * WW);
            const float2 vB = *reinterpret_cast<const float2*>(baseB + j * WW);
            a0 = fmaxf(a0, vA.x); a1 = fmaxf(a1, vA.y);
            b0 = fmaxf(b0, vB.x); b1 = fmaxf(b1, vB.y);
        }
    }
    for (int xx = sbox.xa + 8 + chunk; xx < xe; xx += 4) {
        for (int j = 0; j < hgt; ++j) {
            a0 = fmaxf(a0, __ldg(feat + ((size_t)(b * CC + c)) * HWSZ
                                      + (y1 + j) * WW + xx));
            b0 = fmaxf(b0, __ldg(feat + ((size_t)(b * CC + c + 128)) * HWSZ
                                      + (y1 + j) * WW + xx));
        }
    }

    // Apply column validity once: component k is x = xb + k.
    const bool ok0 = (xb + 0 >= x1) && (xb + 0 < xe);
    const bool ok1 = (xb + 1 >= x1) && (xb + 1 < xe);
    float va = fmaxf(ok0 ? a0 : -INFINITY, ok1 ? a1 : -INFINITY);
    float vb = fmaxf(ok0 ? b0 : -INFINITY, ok1 ? b1 : -INFINITY);

    // Reduce across the 4 chunk lanes (xor 1,2 stays within the group).
    va = fmaxf(va, __shfl_xor_sync(0xFFFFFFFFu, va, 1));
    vb = fmaxf(vb, __shfl_xor_sync(0xFFFFFFFFu, vb, 1));
    va = fmaxf(va, __shfl_xor_sync(0xFFFFFFFFu, va, 2));
    vb = fmaxf(vb, __shfl_xor_sync(0xFFFFFFFFu, vb, 2));

    if (chunk == 0) {
        out[(size_t)bn * CC + c]       = va;  // 8 lanes -> 32B contiguous
        out[(size_t)bn * CC + c + 128] = vb;
    }
}

extern "C" void kernel_launch(void* const* d_in, const int* in_sizes, int n_in,
                              void* d_out, int out_size)
{
    const float* feat = (const float*)d_in[0];   // [B, C, H, W]
    const float* rois = (const float*)d_in[1];   // [B, N, 4]
    float* out        = (float*)d_out;           // [B, N, C]
    (void)in_sizes; (void)n_in; (void)out_size;

    dim3 grid(BB * NN, 2);                       // 512 blocks -> single wave
    roipool_fused_kernel<<<grid, 512>>>(feat, rois, out);
}